// round 8
// baseline (speedup 1.0000x reference)
#include <cuda_runtime.h>
#include <cstdint>
#include <math.h>

#define NROWS   100000
#define NFEAT   512
#define NHID    256
#define NCLASS  41

// ---------------- scratch (device globals) ----------------------------------
__device__ float4 g_buf1_v[(size_t)NROWS * NHID / 4];   // XW1, then A@h
__device__ float4 g_buf2_v[(size_t)NROWS * NHID / 4];   // h = relu(A(XW1)+b1)
__device__ int    g_rowptr[NROWS + 1];

// ---------------- row_ptr: lower_bound of i in sorted rows ------------------
__global__ void build_rowptr(const int* __restrict__ rows, int nnz) {
    int i = blockIdx.x * blockDim.x + threadIdx.x;
    if (i > NROWS) return;
    int lo = 0, hi = nnz;
    while (lo < hi) {
        int mid = (lo + hi) >> 1;
        if (rows[mid] < i) lo = mid + 1; else hi = mid;
    }
    g_rowptr[i] = lo;
}

// ---------------- tf32 helpers ----------------------------------------------
__device__ __forceinline__ uint32_t f2tf32(float a) {
    uint32_t r;
    asm("cvt.rna.tf32.f32 %0, %1;" : "=r"(r) : "f"(a));
    return r;
}
__device__ __forceinline__ void split_tf32(float a, uint32_t& hi, uint32_t& lo) {
    hi = f2tf32(a);
    float hf = __uint_as_float(hi);
    lo = f2tf32(a - hf);
}
__device__ __forceinline__ void mma_tf32(float* c, const uint32_t* a, const uint32_t* b) {
    asm volatile(
        "mma.sync.aligned.m16n8k8.row.col.f32.tf32.tf32.f32 "
        "{%0,%1,%2,%3}, {%4,%5,%6,%7}, {%8,%9}, {%0,%1,%2,%3};"
        : "+f"(c[0]), "+f"(c[1]), "+f"(c[2]), "+f"(c[3])
        : "r"(a[0]), "r"(a[1]), "r"(a[2]), "r"(a[3]),
          "r"(b[0]), "r"(b[1]));
}

// ---------------- SGEMM1: 3xTF32, fragment-ordered smem ----------------------
// C[M,256] = A[M,512] @ B[512,256].  Block tile 128x128, BK=16, 256 threads,
// 8 warps as 2(m) x 4(n); warp computes 64x32 via 4x4 m16n8k8 tiles.
// Smem stores hi/lo tiles in MMA-fragment order:
//   A: sA*[kk][mt][lane] = float4 {a0,a1,a2,a3} for m-tile mt, lane
//   B: sB*[kk][nt][lane] = float2 {b0,b1}      for n-tile nt, lane
#define BM 128
#define BN 128
#define BK 16

__global__ __launch_bounds__(256) void sgemm_tf32(const float* __restrict__ A,
                                                  const float* __restrict__ B,
                                                  float* __restrict__ C) {
    __shared__ __align__(16) float4 sAh[2][8][32];    // 8KB
    __shared__ __align__(16) float4 sAl[2][8][32];    // 8KB
    __shared__ __align__(16) float2 sBh[2][16][32];   // 8KB
    __shared__ __align__(16) float2 sBl[2][16][32];   // 8KB

    const int tid  = threadIdx.x;
    const int lane = tid & 31;
    const int warp = tid >> 5;
    const int warp_m = warp & 1;     // 0..1 -> 64 rows
    const int warp_n = warp >> 1;    // 0..3 -> 32 cols
    const int row0 = blockIdx.x * BM;
    const int col0 = blockIdx.y * BN;

    const int tr = lane >> 2;        // 0..7
    const int tc = lane & 3;         // 0..3

    float acc[4][4][4];
#pragma unroll
    for (int i = 0; i < 4; i++)
#pragma unroll
        for (int j = 0; j < 4; j++)
#pragma unroll
            for (int q = 0; q < 4; q++) acc[i][j][q] = 0.f;

    for (int k0 = 0; k0 < NFEAT; k0 += BK) {
        // ---- stage A tile (128x16), split, fragment order ----
#pragma unroll
        for (int q = 0; q < 2; q++) {
            int idx = q * 256 + tid;              // 0..511
            int r   = idx >> 2;                   // 0..127
            int c4  = (idx & 3) * 4;              // 0,4,8,12
            float4 v = {0.f, 0.f, 0.f, 0.f};
            if (row0 + r < NROWS)
                v = *(const float4*)(A + (size_t)(row0 + r) * NFEAT + k0 + c4);
            int kk = c4 >> 3;                     // 0..1
            int e  = ((r >> 3) & 1) + 2 * ((c4 >> 2) & 1);  // frag component
            int mt = r >> 4;
            int lb = (r & 7) * 4;
            float fv[4] = {v.x, v.y, v.z, v.w};
#pragma unroll
            for (int j = 0; j < 4; j++) {
                uint32_t h, l;
                split_tf32(fv[j], h, l);
                ((uint32_t*)&sAh[kk][mt][lb + j])[e] = h;
                ((uint32_t*)&sAl[kk][mt][lb + j])[e] = l;
            }
        }
        // ---- stage B tile (16x128), split, fragment order ----
#pragma unroll
        for (int q = 0; q < 2; q++) {
            int idx = q * 256 + tid;              // 0..511
            int kr  = idx >> 5;                   // 0..15
            int n0  = (idx & 31) * 4;             // 0..124
            float4 v = *(const float4*)(B + (size_t)(k0 + kr) * NHID + col0 + n0);
            int kk   = kr >> 3;
            int half = (kr >> 2) & 1;
            int btc  = kr & 3;
            float fv[4] = {v.x, v.y, v.z, v.w};
#pragma unroll
            for (int j = 0; j < 4; j++) {
                int n = n0 + j;
                uint32_t h, l;
                split_tf32(fv[j], h, l);
                ((uint32_t*)&sBh[kk][n >> 3][(n & 7) * 4 + btc])[half] = h;
                ((uint32_t*)&sBl[kk][n >> 3][(n & 7) * 4 + btc])[half] = l;
            }
        }
        __syncthreads();

#pragma unroll
        for (int kk = 0; kk < 2; kk++) {
            float4 ah[4], al[4];
            float2 bh[4], bl[4];
#pragma unroll
            for (int wm = 0; wm < 4; wm++) {
                ah[wm] = sAh[kk][warp_m * 4 + wm][lane];
                al[wm] = sAl[kk][warp_m * 4 + wm][lane];
            }
#pragma unroll
            for (int wn = 0; wn < 4; wn++) {
                bh[wn] = sBh[kk][warp_n * 4 + wn][lane];
                bl[wn] = sBl[kk][warp_n * 4 + wn][lane];
            }
            // term-outer order: acc reuse distance = 16 MMAs
#pragma unroll
            for (int wm = 0; wm < 4; wm++)
#pragma unroll
                for (int wn = 0; wn < 4; wn++)
                    mma_tf32(acc[wm][wn], (const uint32_t*)&ah[wm], (const uint32_t*)&bh[wn]);
#pragma unroll
            for (int wm = 0; wm < 4; wm++)
#pragma unroll
                for (int wn = 0; wn < 4; wn++)
                    mma_tf32(acc[wm][wn], (const uint32_t*)&ah[wm], (const uint32_t*)&bl[wn]);
#pragma unroll
            for (int wm = 0; wm < 4; wm++)
#pragma unroll
                for (int wn = 0; wn < 4; wn++)
                    mma_tf32(acc[wm][wn], (const uint32_t*)&al[wm], (const uint32_t*)&bh[wn]);
        }
        __syncthreads();
    }

    // ---- epilogue ----
#pragma unroll
    for (int wm = 0; wm < 4; wm++) {
        int r = row0 + warp_m * 64 + wm * 16 + tr;
#pragma unroll
        for (int wn = 0; wn < 4; wn++) {
            int c = col0 + warp_n * 32 + wn * 8 + tc * 2;
            if (r < NROWS) {
                float2 v = {acc[wm][wn][0], acc[wm][wn][1]};
                *(float2*)(C + (size_t)r * NHID + c) = v;
            }
            if (r + 8 < NROWS) {
                float2 v = {acc[wm][wn][2], acc[wm][wn][3]};
                *(float2*)(C + (size_t)(r + 8) * NHID + c) = v;
            }
        }
    }
}

// ---------------- SpMM (CSR, warp per row), feature-chunked ------------------
// Each launch handles 128 of the 256 feature columns (chunk 0 or 1) so the
// gathered dense working set (~51MB) stays L2-resident.
__global__ __launch_bounds__(256) void spmm_chunk(const int* __restrict__ cols,
                                                  const float* __restrict__ vals,
                                                  const float4* __restrict__ dense,
                                                  const float* __restrict__ bias,
                                                  float4* __restrict__ out,
                                                  int do_relu, int chunk) {
    int row  = blockIdx.x * (blockDim.x >> 5) + (threadIdx.x >> 5);
    if (row >= NROWS) return;
    int lane = threadIdx.x & 31;
    const int coff = chunk * 32 + lane;          // float4 index within row

    int s = g_rowptr[row];
    int e = g_rowptr[row + 1];

    float4 acc = {0.f, 0.f, 0.f, 0.f};

    for (int j = s; j < e; j++) {
        int   c = __ldg(cols + j);
        float v = __ldg(vals + j);
        float4 d = __ldg(dense + (size_t)c * (NHID / 4) + coff);
        acc.x += v * d.x; acc.y += v * d.y; acc.z += v * d.z; acc.w += v * d.w;
    }

    if (bias) {
        int c0 = coff * 4;
        acc.x += __ldg(bias + c0);     acc.y += __ldg(bias + c0 + 1);
        acc.z += __ldg(bias + c0 + 2); acc.w += __ldg(bias + c0 + 3);
    }
    if (do_relu) {
        acc.x = fmaxf(acc.x, 0.f); acc.y = fmaxf(acc.y, 0.f);
        acc.z = fmaxf(acc.z, 0.f); acc.w = fmaxf(acc.w, 0.f);
    }

    out[(size_t)row * (NHID / 4) + coff] = acc;
}

// ---------------- GEMM2 (256->41) + bias + log_softmax, fused ---------------
__global__ __launch_bounds__(256) void gemm2_lsm(const float4* __restrict__ ah,
                                                 const float* __restrict__ w2,
                                                 const float* __restrict__ b2,
                                                 float* __restrict__ out) {
    __shared__ __align__(16) float sw[NHID * NCLASS];   // 41984 B
    __shared__ __align__(16) float srow[4][NHID];
    __shared__ __align__(16) float slog[4][NCLASS];
    __shared__ __align__(16) float sb[NCLASS];

    const int tid = threadIdx.x;
    for (int i = tid; i < NHID * NCLASS; i += 256) sw[i] = w2[i];
    if (tid < NCLASS) sb[tid] = b2[tid];
    __syncthreads();

    const int group = tid >> 6;   // 0..3
    const int gt    = tid & 63;   // 0..63

    for (int row0 = blockIdx.x * 4; row0 < NROWS; row0 += gridDim.x * 4) {
        const int row = row0 + group;
        const bool rok = row < NROWS;

        if (rok) {
            float4 v = ah[(size_t)row * (NHID / 4) + gt];
            ((float4*)srow[group])[gt] = v;
        }
        __syncthreads();

        if (rok && gt < NCLASS) {
            float a = sb[gt];
#pragma unroll 8
            for (int k = 0; k < NHID; k++)
                a += srow[group][k] * sw[k * NCLASS + gt];
            slog[group][gt] = a;
        }
        __syncthreads();

        if (rok && gt < NCLASS) {
            float m = -INFINITY;
#pragma unroll
            for (int k = 0; k < NCLASS; k++) m = fmaxf(m, slog[group][k]);
            float ssum = 0.f;
#pragma unroll
            for (int k = 0; k < NCLASS; k++) ssum += expf(slog[group][k] - m);
            out[(size_t)row * NCLASS + gt] = slog[group][gt] - m - logf(ssum);
        }
        __syncthreads();
    }
}

// -----------------------------------------------------------------------------
extern "C" void kernel_launch(void* const* d_in, const int* in_sizes, int n_in,
                              void* d_out, int out_size) {
    const float* x        = (const float*)d_in[0];
    const int*   adj_rows = (const int*)  d_in[1];
    const int*   adj_cols = (const int*)  d_in[2];
    const float* adj_vals = (const float*)d_in[3];
    const float* w1       = (const float*)d_in[4];
    const float* b1       = (const float*)d_in[5];
    const float* w2       = (const float*)d_in[6];
    const float* b2       = (const float*)d_in[7];
    float* out = (float*)d_out;
    const int nnz = in_sizes[1];

    float4* buf1; cudaGetSymbolAddress((void**)&buf1, g_buf1_v);
    float4* buf2; cudaGetSymbolAddress((void**)&buf2, g_buf2_v);

    // 1) CSR row pointers from sorted rows
    build_rowptr<<<(NROWS + 1 + 255) / 256, 256>>>(adj_rows, nnz);

    // 2) XW1 -> buf1 (3xTF32 tensor GEMM, fragment-ordered smem)
    dim3 g1((NROWS + BM - 1) / BM, NHID / BN);
    sgemm_tf32<<<g1, 256>>>(x, w1, (float*)buf1);

    // 3) h = relu(A @ buf1 + b1) -> buf2   (two feature chunks)
    int spmm_blocks = (NROWS * 32 + 255) / 256;
    spmm_chunk<<<spmm_blocks, 256>>>(adj_cols, adj_vals, buf1, b1, buf2, 1, 0);
    spmm_chunk<<<spmm_blocks, 256>>>(adj_cols, adj_vals, buf1, b1, buf2, 1, 1);

    // 4) A @ h -> buf1   (two feature chunks)
    spmm_chunk<<<spmm_blocks, 256>>>(adj_cols, adj_vals, buf2, nullptr, buf1, 0, 0);
    spmm_chunk<<<spmm_blocks, 256>>>(adj_cols, adj_vals, buf2, nullptr, buf1, 0, 1);

    // 5) log_softmax(buf1 @ W2 + b2) -> out
    gemm2_lsm<<<2048, 256>>>(buf1, w2, b2, out);
}

// round 9
// speedup vs baseline: 2.3935x; 2.3935x over previous
#include <cuda_runtime.h>
#include <cstdint>
#include <math.h>

#define NROWS   100000
#define NFEAT   512
#define NHID    256
#define NCLASS  41
#define TPAD    44          // t row padded to 44 floats (11 float4)

// ---------------- scratch (device globals) ----------------------------------
__device__ float4 g_buf1_v[(size_t)NROWS * NHID / 4];   // XW1, then t (padded 44)
__device__ float4 g_buf2_v[(size_t)NROWS * NHID / 4];   // h = relu(A(XW1)+b1)
__device__ int    g_rowptr[NROWS + 1];

// ---------------- row_ptr: lower_bound of i in sorted rows ------------------
__global__ void build_rowptr(const int* __restrict__ rows, int nnz) {
    int i = blockIdx.x * blockDim.x + threadIdx.x;
    if (i > NROWS) return;
    int lo = 0, hi = nnz;
    while (lo < hi) {
        int mid = (lo + hi) >> 1;
        if (rows[mid] < i) lo = mid + 1; else hi = mid;
    }
    g_rowptr[i] = lo;
}

// ---------------- tf32 helpers ----------------------------------------------
__device__ __forceinline__ uint32_t f2tf32(float a) {
    uint32_t r;
    asm("cvt.rna.tf32.f32 %0, %1;" : "=r"(r) : "f"(a));
    return r;
}
__device__ __forceinline__ void mma_tf32(float* c, const uint32_t* a, const uint32_t* b) {
    asm volatile(
        "mma.sync.aligned.m16n8k8.row.col.f32.tf32.tf32.f32 "
        "{%0,%1,%2,%3}, {%4,%5,%6,%7}, {%8,%9}, {%0,%1,%2,%3};"
        : "+f"(c[0]), "+f"(c[1]), "+f"(c[2]), "+f"(c[3])
        : "r"(a[0]), "r"(a[1]), "r"(a[2]), "r"(a[3]),
          "r"(b[0]), "r"(b[1]));
}

// ---------------- SGEMM1: single-pass TF32 (R5 layout) -----------------------
// C[M,256] = A[M,512] @ B[512,256].  Block tile 128x128, BK=16, 256 threads,
// 8 warps as 2(m) x 4(n); warp computes 64x32 via 4x4 m16n8k8 tiles.
#define BM 128
#define BN 128
#define BK 16
#define SAP 20      // conflict-free (verified: 20*tr+tc distinct mod 32)
#define SBP 136     // conflict-free (8*tc+tr distinct mod 32)

__global__ __launch_bounds__(256) void sgemm_tf32(const float* __restrict__ A,
                                                  const float* __restrict__ B,
                                                  float* __restrict__ C) {
    __shared__ __align__(16) uint32_t sA[BM][SAP];
    __shared__ __align__(16) uint32_t sB[BK][SBP];

    const int tid  = threadIdx.x;
    const int lane = tid & 31;
    const int warp = tid >> 5;
    const int warp_m = warp & 1;
    const int warp_n = warp >> 1;
    const int row0 = blockIdx.x * BM;
    const int col0 = blockIdx.y * BN;

    const int tr = lane >> 2;
    const int tc = lane & 3;

    float acc[4][4][4];
#pragma unroll
    for (int i = 0; i < 4; i++)
#pragma unroll
        for (int j = 0; j < 4; j++)
#pragma unroll
            for (int q = 0; q < 4; q++) acc[i][j][q] = 0.f;

    for (int k0 = 0; k0 < NFEAT; k0 += BK) {
#pragma unroll
        for (int q = 0; q < 2; q++) {
            int idx = tid * 2 + q;
            int r = idx >> 2, c4 = (idx & 3) * 4;
            float4 v = {0.f, 0.f, 0.f, 0.f};
            if (row0 + r < NROWS)
                v = *(const float4*)(A + (size_t)(row0 + r) * NFEAT + k0 + c4);
            sA[r][c4 + 0] = f2tf32(v.x);
            sA[r][c4 + 1] = f2tf32(v.y);
            sA[r][c4 + 2] = f2tf32(v.z);
            sA[r][c4 + 3] = f2tf32(v.w);
        }
#pragma unroll
        for (int q = 0; q < 2; q++) {
            int idx = tid * 2 + q;
            int r = idx >> 5, c4 = (idx & 31) * 4;
            float4 v = *(const float4*)(B + (size_t)(k0 + r) * NHID + col0 + c4);
            sB[r][c4 + 0] = f2tf32(v.x);
            sB[r][c4 + 1] = f2tf32(v.y);
            sB[r][c4 + 2] = f2tf32(v.z);
            sB[r][c4 + 3] = f2tf32(v.w);
        }
        __syncthreads();

#pragma unroll
        for (int kk = 0; kk < BK; kk += 8) {
            uint32_t bh[4][2];
#pragma unroll
            for (int wn = 0; wn < 4; wn++) {
                int n = warp_n * 32 + wn * 8 + tr;
                bh[wn][0] = sB[kk + tc][n];
                bh[wn][1] = sB[kk + tc + 4][n];
            }
#pragma unroll
            for (int wm = 0; wm < 4; wm++) {
                int m = warp_m * 64 + wm * 16 + tr;
                uint32_t ah[4];
                ah[0] = sA[m][kk + tc];
                ah[1] = sA[m + 8][kk + tc];
                ah[2] = sA[m][kk + tc + 4];
                ah[3] = sA[m + 8][kk + tc + 4];
#pragma unroll
                for (int wn = 0; wn < 4; wn++)
                    mma_tf32(acc[wm][wn], ah, bh[wn]);
            }
        }
        __syncthreads();
    }

#pragma unroll
    for (int wm = 0; wm < 4; wm++) {
        int r = row0 + warp_m * 64 + wm * 16 + tr;
#pragma unroll
        for (int wn = 0; wn < 4; wn++) {
            int c = col0 + warp_n * 32 + wn * 8 + tc * 2;
            if (r < NROWS) {
                float2 v = {acc[wm][wn][0], acc[wm][wn][1]};
                *(float2*)(C + (size_t)r * NHID + c) = v;
            }
            if (r + 8 < NROWS) {
                float2 v = {acc[wm][wn][2], acc[wm][wn][3]};
                *(float2*)(C + (size_t)(r + 8) * NHID + c) = v;
            }
        }
    }
}

// ---------------- SpMM layer 1 (CSR, warp/row, feature-chunked) --------------
__global__ __launch_bounds__(256) void spmm_chunk(const int* __restrict__ cols,
                                                  const float* __restrict__ vals,
                                                  const float4* __restrict__ dense,
                                                  const float* __restrict__ bias,
                                                  float4* __restrict__ out,
                                                  int chunk) {
    int row  = blockIdx.x * (blockDim.x >> 5) + (threadIdx.x >> 5);
    if (row >= NROWS) return;
    int lane = threadIdx.x & 31;
    const int coff = chunk * 32 + lane;

    int s = g_rowptr[row];
    int e = g_rowptr[row + 1];

    float4 acc = {0.f, 0.f, 0.f, 0.f};
    for (int j = s; j < e; j++) {
        int   c = __ldg(cols + j);
        float v = __ldg(vals + j);
        float4 d = __ldg(dense + (size_t)c * (NHID / 4) + coff);
        acc.x += v * d.x; acc.y += v * d.y; acc.z += v * d.z; acc.w += v * d.w;
    }

    int c0 = coff * 4;
    acc.x = fmaxf(acc.x + __ldg(bias + c0),     0.f);
    acc.y = fmaxf(acc.y + __ldg(bias + c0 + 1), 0.f);
    acc.z = fmaxf(acc.z + __ldg(bias + c0 + 2), 0.f);
    acc.w = fmaxf(acc.w + __ldg(bias + c0 + 3), 0.f);

    out[(size_t)row * (NHID / 4) + coff] = acc;
}

// ---------------- t = h @ W2  (256->41, padded to 44) ------------------------
__global__ __launch_bounds__(256) void gemm_t(const float4* __restrict__ h,
                                              const float* __restrict__ w2,
                                              float* __restrict__ t) {
    __shared__ __align__(16) float sw[NHID * NCLASS];
    __shared__ __align__(16) float srow[4][NHID];

    const int tid = threadIdx.x;
    for (int i = tid; i < NHID * NCLASS; i += 256) sw[i] = w2[i];
    __syncthreads();

    const int group = tid >> 6;
    const int gt    = tid & 63;

    for (int row0 = blockIdx.x * 4; row0 < NROWS; row0 += gridDim.x * 4) {
        const int row = row0 + group;
        const bool rok = row < NROWS;

        if (rok) {
            float4 v = h[(size_t)row * (NHID / 4) + gt];
            ((float4*)srow[group])[gt] = v;
        }
        __syncthreads();

        if (rok && gt < TPAD) {
            float a = 0.f;
            if (gt < NCLASS) {
#pragma unroll 8
                for (int k = 0; k < NHID; k++)
                    a += srow[group][k] * sw[k * NCLASS + gt];
            }
            t[(size_t)row * TPAD + gt] = a;
        }
        __syncthreads();
    }
}

// ---------------- SpMM layer 2 + b2 + log_softmax, fused ---------------------
// out[row,:] = log_softmax( sum_j vals[j] * t[cols[j],:] + b2 )
// t rows are 44 floats (11 float4, cols 41..43 zero) -> 17.6MB, L2-resident.
__global__ __launch_bounds__(256) void spmm2_lsm(const int* __restrict__ cols,
                                                 const float* __restrict__ vals,
                                                 const float4* __restrict__ t,
                                                 const float* __restrict__ b2,
                                                 float* __restrict__ out) {
    int row  = blockIdx.x * (blockDim.x >> 5) + (threadIdx.x >> 5);
    if (row >= NROWS) return;
    int lane = threadIdx.x & 31;
    const bool active = lane < (TPAD / 4);   // lanes 0..10 gather

    int s = g_rowptr[row];
    int e = g_rowptr[row + 1];

    float4 acc = {0.f, 0.f, 0.f, 0.f};
    for (int j = s; j < e; j++) {
        int   c = __ldg(cols + j);
        float v = __ldg(vals + j);
        if (active) {
            float4 d = __ldg(t + (size_t)c * (TPAD / 4) + lane);
            acc.x += v * d.x; acc.y += v * d.y; acc.z += v * d.z; acc.w += v * d.w;
        }
    }

    // bias + log_softmax over 41 valid columns
    float z[4];
    const int c0 = lane * 4;
#pragma unroll
    for (int i = 0; i < 4; i++) {
        int c = c0 + i;
        z[i] = (c < NCLASS) ? ((&acc.x)[i] + __ldg(b2 + c)) : -INFINITY;
    }
    float m = fmaxf(fmaxf(z[0], z[1]), fmaxf(z[2], z[3]));
#pragma unroll
    for (int off = 16; off; off >>= 1)
        m = fmaxf(m, __shfl_xor_sync(0xFFFFFFFFu, m, off));

    float ss = 0.f;
#pragma unroll
    for (int i = 0; i < 4; i++)
        if (c0 + i < NCLASS) ss += expf(z[i] - m);
#pragma unroll
    for (int off = 16; off; off >>= 1)
        ss += __shfl_xor_sync(0xFFFFFFFFu, ss, off);

    float lse = m + logf(ss);
#pragma unroll
    for (int i = 0; i < 4; i++) {
        int c = c0 + i;
        if (c < NCLASS) out[(size_t)row * NCLASS + c] = z[i] - lse;
    }
}

// -----------------------------------------------------------------------------
extern "C" void kernel_launch(void* const* d_in, const int* in_sizes, int n_in,
                              void* d_out, int out_size) {
    const float* x        = (const float*)d_in[0];
    const int*   adj_rows = (const int*)  d_in[1];
    const int*   adj_cols = (const int*)  d_in[2];
    const float* adj_vals = (const float*)d_in[3];
    const float* w1       = (const float*)d_in[4];
    const float* b1       = (const float*)d_in[5];
    const float* w2       = (const float*)d_in[6];
    const float* b2       = (const float*)d_in[7];
    float* out = (float*)d_out;
    const int nnz = in_sizes[1];

    float4* buf1; cudaGetSymbolAddress((void**)&buf1, g_buf1_v);
    float4* buf2; cudaGetSymbolAddress((void**)&buf2, g_buf2_v);

    // 1) CSR row pointers from sorted rows
    build_rowptr<<<(NROWS + 1 + 255) / 256, 256>>>(adj_rows, nnz);

    // 2) XW1 -> buf1 (single-pass TF32 tensor GEMM)
    dim3 g1((NROWS + BM - 1) / BM, NHID / BN);
    sgemm_tf32<<<g1, 256>>>(x, w1, (float*)buf1);

    // 3) h = relu(A @ buf1 + b1) -> buf2  (two L2-resident feature chunks)
    int spmm_blocks = (NROWS * 32 + 255) / 256;
    spmm_chunk<<<spmm_blocks, 256>>>(adj_cols, adj_vals, buf1, b1, buf2, 0);
    spmm_chunk<<<spmm_blocks, 256>>>(adj_cols, adj_vals, buf1, b1, buf2, 1);

    // 4) t = h @ W2 -> buf1 (44-float padded rows)
    gemm_t<<<2048, 256>>>(buf2, w2, (float*)buf1);

    // 5) out = log_softmax(A @ t + b2)  (t is L2-resident: 17.6MB)
    spmm2_lsm<<<spmm_blocks, 256>>>(adj_cols, adj_vals, buf1, b2, out);
}

// round 10
// speedup vs baseline: 3.3342x; 1.3931x over previous
#include <cuda_runtime.h>
#include <cstdint>
#include <math.h>

#define NROWS   100000
#define NFEAT   512
#define NHID    256
#define NCLASS  41
#define TPAD    44          // t row padded to 44 floats (11 float4)
#define W2PN    64          // W2 padded cols

// ---------------- scratch (device globals) ----------------------------------
__device__ float4 g_buf1_v[(size_t)NROWS * NHID / 4];   // XW1, then t (44-pitch)
__device__ float4 g_buf2_v[(size_t)NROWS * NHID / 4];   // h
__device__ int    g_rowptr[NROWS + 1];
__device__ __align__(16) uint32_t g_w1t[NFEAT * NHID];  // W1 as tf32 bits
__device__ __align__(16) uint32_t g_w2t[NHID * W2PN];   // W2 padded, tf32 bits

// ---------------- row_ptr ----------------------------------------------------
__global__ void build_rowptr(const int* __restrict__ rows, int nnz) {
    int i = blockIdx.x * blockDim.x + threadIdx.x;
    if (i > NROWS) return;
    int lo = 0, hi = nnz;
    while (lo < hi) {
        int mid = (lo + hi) >> 1;
        if (rows[mid] < i) lo = mid + 1; else hi = mid;
    }
    g_rowptr[i] = lo;
}

// ---------------- tf32 helpers ----------------------------------------------
__device__ __forceinline__ uint32_t f2tf32(float a) {
    uint32_t r;
    asm("cvt.rna.tf32.f32 %0, %1;" : "=r"(r) : "f"(a));
    return r;
}
__device__ __forceinline__ void mma_tf32(float* c, const uint32_t* a, const uint32_t* b) {
    asm volatile(
        "mma.sync.aligned.m16n8k8.row.col.f32.tf32.tf32.f32 "
        "{%0,%1,%2,%3}, {%4,%5,%6,%7}, {%8,%9}, {%0,%1,%2,%3};"
        : "+f"(c[0]), "+f"(c[1]), "+f"(c[2]), "+f"(c[3])
        : "r"(a[0]), "r"(a[1]), "r"(a[2]), "r"(a[3]),
          "r"(b[0]), "r"(b[1]));
}

// ---------------- prep: tf32 images of W1 / padded W2 ------------------------
__global__ void prep_w1(const float* __restrict__ w1) {
    int i = blockIdx.x * blockDim.x + threadIdx.x;
    if (i < NFEAT * NHID) g_w1t[i] = f2tf32(w1[i]);
}
__global__ void prep_w2(const float* __restrict__ w2) {
    int i = blockIdx.x * blockDim.x + threadIdx.x;
    if (i >= NHID * W2PN) return;
    int k = i / W2PN, n = i % W2PN;
    g_w2t[i] = (n < NCLASS) ? f2tf32(w2[k * NCLASS + n]) : 0u;
}

// ---------------- SGEMM1: TF32, double-buffered ------------------------------
#define BM 128
#define BN 128
#define BK 16
#define SAP 20
#define SBP 136

__device__ __forceinline__ void ldgA16(const float* A, int row0, int k0, int tid,
                                       float4 ra[2]) {
#pragma unroll
    for (int q = 0; q < 2; q++) {
        int idx = tid * 2 + q;
        int r = idx >> 2, c4 = (idx & 3) * 4;
        float4 v = {0.f, 0.f, 0.f, 0.f};
        if (row0 + r < NROWS)
            v = *(const float4*)(A + (size_t)(row0 + r) * NFEAT + k0 + c4);
        ra[q] = v;
    }
}
__device__ __forceinline__ void ldgB16(const uint32_t* Bt, int col0, int k0, int tid,
                                       uint4 rb[2]) {
#pragma unroll
    for (int q = 0; q < 2; q++) {
        int idx = tid * 2 + q;
        int r = idx >> 5, c4 = (idx & 31) * 4;
        rb[q] = *(const uint4*)(Bt + (size_t)(k0 + r) * NHID + col0 + c4);
    }
}
__device__ __forceinline__ void stsAB16(uint32_t (*sA)[SAP], uint32_t (*sB)[SBP],
                                        int tid, const float4 ra[2], const uint4 rb[2]) {
#pragma unroll
    for (int q = 0; q < 2; q++) {
        int idx = tid * 2 + q;
        int r = idx >> 2, c4 = (idx & 3) * 4;
        uint4 u = {f2tf32(ra[q].x), f2tf32(ra[q].y), f2tf32(ra[q].z), f2tf32(ra[q].w)};
        *(uint4*)&sA[r][c4] = u;
    }
#pragma unroll
    for (int q = 0; q < 2; q++) {
        int idx = tid * 2 + q;
        int r = idx >> 5, c4 = (idx & 31) * 4;
        *(uint4*)&sB[r][c4] = rb[q];
    }
}

__global__ __launch_bounds__(256) void sgemm_db(const float* __restrict__ A,
                                                const uint32_t* __restrict__ Bt,
                                                float* __restrict__ C) {
    __shared__ __align__(16) uint32_t sA[2][BM][SAP];
    __shared__ __align__(16) uint32_t sB[2][BK][SBP];

    const int tid  = threadIdx.x;
    const int lane = tid & 31;
    const int warp = tid >> 5;
    const int warp_m = warp & 1;
    const int warp_n = warp >> 1;
    const int row0 = blockIdx.x * BM;
    const int col0 = blockIdx.y * BN;
    const int tr = lane >> 2;
    const int tc = lane & 3;

    float acc[4][4][4];
#pragma unroll
    for (int i = 0; i < 4; i++)
#pragma unroll
        for (int j = 0; j < 4; j++)
#pragma unroll
            for (int q = 0; q < 4; q++) acc[i][j][q] = 0.f;

    float4 ra[2]; uint4 rb[2];
    ldgA16(A, row0, 0, tid, ra);
    ldgB16(Bt, col0, 0, tid, rb);
    stsAB16(sA[0], sB[0], tid, ra, rb);
    __syncthreads();

    const int NT = NFEAT / BK;
    for (int t = 0; t < NT; t++) {
        const int cur = t & 1;
        if (t + 1 < NT) {
            ldgA16(A, row0, (t + 1) * BK, tid, ra);
            ldgB16(Bt, col0, (t + 1) * BK, tid, rb);
        }
#pragma unroll
        for (int kk = 0; kk < BK; kk += 8) {
            uint32_t bf[4][2];
#pragma unroll
            for (int wn = 0; wn < 4; wn++) {
                int n = warp_n * 32 + wn * 8 + tr;
                bf[wn][0] = sB[cur][kk + tc][n];
                bf[wn][1] = sB[cur][kk + tc + 4][n];
            }
#pragma unroll
            for (int wm = 0; wm < 4; wm++) {
                int m = warp_m * 64 + wm * 16 + tr;
                uint32_t af[4];
                af[0] = sA[cur][m][kk + tc];
                af[1] = sA[cur][m + 8][kk + tc];
                af[2] = sA[cur][m][kk + tc + 4];
                af[3] = sA[cur][m + 8][kk + tc + 4];
#pragma unroll
                for (int wn = 0; wn < 4; wn++)
                    mma_tf32(acc[wm][wn], af, bf[wn]);
            }
        }
        if (t + 1 < NT)
            stsAB16(sA[cur ^ 1], sB[cur ^ 1], tid, ra, rb);
        __syncthreads();
    }

#pragma unroll
    for (int wm = 0; wm < 4; wm++) {
        int r = row0 + warp_m * 64 + wm * 16 + tr;
#pragma unroll
        for (int wn = 0; wn < 4; wn++) {
            int c = col0 + warp_n * 32 + wn * 8 + tc * 2;
            if (r < NROWS) {
                float2 v = {acc[wm][wn][0], acc[wm][wn][1]};
                *(float2*)(C + (size_t)r * NHID + c) = v;
            }
            if (r + 8 < NROWS) {
                float2 v = {acc[wm][wn][2], acc[wm][wn][3]};
                *(float2*)(C + (size_t)(r + 8) * NHID + c) = v;
            }
        }
    }
}

// ---------------- SpMM layer 1 (CSR, warp/row, feature-chunked) --------------
__global__ __launch_bounds__(256) void spmm_chunk(const int* __restrict__ cols,
                                                  const float* __restrict__ vals,
                                                  const float4* __restrict__ dense,
                                                  const float* __restrict__ bias,
                                                  float4* __restrict__ out,
                                                  int chunk) {
    int row  = blockIdx.x * (blockDim.x >> 5) + (threadIdx.x >> 5);
    if (row >= NROWS) return;
    int lane = threadIdx.x & 31;
    const int coff = chunk * 32 + lane;

    int s = g_rowptr[row];
    int e = g_rowptr[row + 1];

    float4 acc = {0.f, 0.f, 0.f, 0.f};
    for (int j = s; j < e; j++) {
        int   c = __ldg(cols + j);
        float v = __ldg(vals + j);
        float4 d = __ldg(dense + (size_t)c * (NHID / 4) + coff);
        acc.x += v * d.x; acc.y += v * d.y; acc.z += v * d.z; acc.w += v * d.w;
    }

    int c0 = coff * 4;
    acc.x = fmaxf(acc.x + __ldg(bias + c0),     0.f);
    acc.y = fmaxf(acc.y + __ldg(bias + c0 + 1), 0.f);
    acc.z = fmaxf(acc.z + __ldg(bias + c0 + 2), 0.f);
    acc.w = fmaxf(acc.w + __ldg(bias + c0 + 3), 0.f);

    out[(size_t)row * (NHID / 4) + coff] = acc;
}

// ---------------- t = h @ W2pad  via TF32 MMA (128x64 tile) ------------------
#define TBM 128
#define TBN 64
#define TBK 32
#define TSAP 36     // 4*tr+tc distinct mod 32
#define TSBP 72     // 8*tc+tr distinct mod 32

__global__ __launch_bounds__(256) void gemm_t_tc(const float* __restrict__ H,
                                                 const uint32_t* __restrict__ Bt,
                                                 float* __restrict__ T) {
    __shared__ __align__(16) uint32_t sA[TBM][TSAP];
    __shared__ __align__(16) uint32_t sB[TBK][TSBP];

    const int tid  = threadIdx.x;
    const int lane = tid & 31;
    const int warp = tid >> 5;
    const int warp_m = warp & 1;     // 0..1 -> 64 rows
    const int warp_n = warp >> 1;    // 0..3 -> 16 cols
    const int row0 = blockIdx.x * TBM;
    const int tr = lane >> 2;
    const int tc = lane & 3;

    float acc[4][2][4];
#pragma unroll
    for (int i = 0; i < 4; i++)
#pragma unroll
        for (int j = 0; j < 2; j++)
#pragma unroll
            for (int q = 0; q < 4; q++) acc[i][j][q] = 0.f;

    for (int k0 = 0; k0 < NHID; k0 += TBK) {
        // A: 128x32 floats = 1024 float4, 4/thread
#pragma unroll
        for (int q = 0; q < 4; q++) {
            int idx = q * 256 + tid;
            int r = idx >> 3, c4 = (idx & 7) * 4;
            float4 v = {0.f, 0.f, 0.f, 0.f};
            if (row0 + r < NROWS)
                v = *(const float4*)(H + (size_t)(row0 + r) * NHID + k0 + c4);
            uint4 u = {f2tf32(v.x), f2tf32(v.y), f2tf32(v.z), f2tf32(v.w)};
            *(uint4*)&sA[r][c4] = u;
        }
        // B: 32x64 tf32 = 512 uint4, 2/thread
#pragma unroll
        for (int q = 0; q < 2; q++) {
            int idx = q * 256 + tid;
            int r = idx >> 4, c4 = (idx & 15) * 4;
            *(uint4*)&sB[r][c4] = *(const uint4*)(Bt + (size_t)(k0 + r) * W2PN + c4);
        }
        __syncthreads();

#pragma unroll
        for (int kk = 0; kk < TBK; kk += 8) {
            uint32_t bf[2][2];
#pragma unroll
            for (int wn = 0; wn < 2; wn++) {
                int n = warp_n * 16 + wn * 8 + tr;
                bf[wn][0] = sB[kk + tc][n];
                bf[wn][1] = sB[kk + tc + 4][n];
            }
#pragma unroll
            for (int wm = 0; wm < 4; wm++) {
                int m = warp_m * 64 + wm * 16 + tr;
                uint32_t af[4];
                af[0] = sA[m][kk + tc];
                af[1] = sA[m + 8][kk + tc];
                af[2] = sA[m][kk + tc + 4];
                af[3] = sA[m + 8][kk + tc + 4];
#pragma unroll
                for (int wn = 0; wn < 2; wn++)
                    mma_tf32(acc[wm][wn], af, bf[wn]);
            }
        }
        __syncthreads();
    }

    // epilogue -> 44-pitch t rows (cols >= 44 dropped; 41..43 are zero by pad)
#pragma unroll
    for (int wm = 0; wm < 4; wm++) {
        int r = row0 + warp_m * 64 + wm * 16 + tr;
#pragma unroll
        for (int wn = 0; wn < 2; wn++) {
            int c = warp_n * 16 + wn * 8 + tc * 2;
            if (c < TPAD) {
                if (r < NROWS) {
                    float2 v = {acc[wm][wn][0], acc[wm][wn][1]};
                    *(float2*)(T + (size_t)r * TPAD + c) = v;
                }
                if (r + 8 < NROWS) {
                    float2 v = {acc[wm][wn][2], acc[wm][wn][3]};
                    *(float2*)(T + (size_t)(r + 8) * TPAD + c) = v;
                }
            }
        }
    }
}

// ---------------- SpMM layer 2 + b2 + log_softmax, fused ---------------------
__global__ __launch_bounds__(256) void spmm2_lsm(const int* __restrict__ cols,
                                                 const float* __restrict__ vals,
                                                 const float4* __restrict__ t,
                                                 const float* __restrict__ b2,
                                                 float* __restrict__ out) {
    int row  = blockIdx.x * (blockDim.x >> 5) + (threadIdx.x >> 5);
    if (row >= NROWS) return;
    int lane = threadIdx.x & 31;
    const bool active = lane < (TPAD / 4);

    int s = g_rowptr[row];
    int e = g_rowptr[row + 1];

    float4 acc = {0.f, 0.f, 0.f, 0.f};
    for (int j = s; j < e; j++) {
        int   c = __ldg(cols + j);
        float v = __ldg(vals + j);
        if (active) {
            float4 d = __ldg(t + (size_t)c * (TPAD / 4) + lane);
            acc.x += v * d.x; acc.y += v * d.y; acc.z += v * d.z; acc.w += v * d.w;
        }
    }

    float z[4];
    const int c0 = lane * 4;
#pragma unroll
    for (int i = 0; i < 4; i++) {
        int c = c0 + i;
        z[i] = (c < NCLASS) ? ((&acc.x)[i] + __ldg(b2 + c)) : -INFINITY;
    }
    float m = fmaxf(fmaxf(z[0], z[1]), fmaxf(z[2], z[3]));
#pragma unroll
    for (int off = 16; off; off >>= 1)
        m = fmaxf(m, __shfl_xor_sync(0xFFFFFFFFu, m, off));

    float ss = 0.f;
#pragma unroll
    for (int i = 0; i < 4; i++)
        if (c0 + i < NCLASS) ss += expf(z[i] - m);
#pragma unroll
    for (int off = 16; off; off >>= 1)
        ss += __shfl_xor_sync(0xFFFFFFFFu, ss, off);

    float lse = m + logf(ss);
#pragma unroll
    for (int i = 0; i < 4; i++) {
        int c = c0 + i;
        if (c < NCLASS) out[(size_t)row * NCLASS + c] = z[i] - lse;
    }
}

// -----------------------------------------------------------------------------
extern "C" void kernel_launch(void* const* d_in, const int* in_sizes, int n_in,
                              void* d_out, int out_size) {
    const float* x        = (const float*)d_in[0];
    const int*   adj_rows = (const int*)  d_in[1];
    const int*   adj_cols = (const int*)  d_in[2];
    const float* adj_vals = (const float*)d_in[3];
    const float* w1       = (const float*)d_in[4];
    const float* b1       = (const float*)d_in[5];
    const float* w2       = (const float*)d_in[6];
    const float* b2       = (const float*)d_in[7];
    float* out = (float*)d_out;
    const int nnz = in_sizes[1];

    float4* buf1; cudaGetSymbolAddress((void**)&buf1, g_buf1_v);
    float4* buf2; cudaGetSymbolAddress((void**)&buf2, g_buf2_v);
    uint32_t* w1t; cudaGetSymbolAddress((void**)&w1t, g_w1t);
    uint32_t* w2t; cudaGetSymbolAddress((void**)&w2t, g_w2t);

    // 1) CSR row pointers + weight images
    build_rowptr<<<(NROWS + 1 + 255) / 256, 256>>>(adj_rows, nnz);
    prep_w1<<<(NFEAT * NHID + 255) / 256, 256>>>(w1);
    prep_w2<<<(NHID * W2PN + 255) / 256, 256>>>(w2);

    // 2) XW1 -> buf1 (TF32, double-buffered)
    dim3 g1((NROWS + BM - 1) / BM, NHID / BN);
    sgemm_db<<<g1, 256>>>(x, w1t, (float*)buf1);

    // 3) h = relu(A @ buf1 + b1) -> buf2  (two L2-resident feature chunks)
    int spmm_blocks = (NROWS * 32 + 255) / 256;
    spmm_chunk<<<spmm_blocks, 256>>>(adj_cols, adj_vals, buf1, b1, buf2, 0);
    spmm_chunk<<<spmm_blocks, 256>>>(adj_cols, adj_vals, buf1, b1, buf2, 1);

    // 4) t = h @ W2pad -> buf1 (44-pitch, TF32 MMA)
    gemm_t_tc<<<(NROWS + TBM - 1) / TBM, 256>>>((const float*)buf2, w2t, (float*)buf1);

    // 5) out = log_softmax(A @ t + b2)   (t: 17.6MB, L2-resident)
    spmm2_lsm<<<spmm_blocks, 256>>>(adj_cols, adj_vals, buf1, b2, out);
}

// round 11
// speedup vs baseline: 4.2677x; 1.2800x over previous
#include <cuda_runtime.h>
#include <cuda_fp16.h>
#include <cstdint>
#include <math.h>

#define NROWS   100000
#define NFEAT   512
#define NHID    256
#define NCLASS  41
#define TPAD    44          // t row padded to 44 floats (11 float4)
#define W2PN    64          // W2 padded cols

// ---------------- scratch (device globals) ----------------------------------
__device__ float4 g_buf1_v[(size_t)NROWS * NHID / 4];   // XW1, then t (44-pitch)
__device__ float4 g_buf2_v[(size_t)NROWS * NHID / 4];   // h
__device__ int    g_rowptr[NROWS + 1];
// W1 packed as half2 along k: g_w1p[k2 * NHID + n] = (w1[2k2][n], w1[2k2+1][n])
__device__ __align__(16) uint32_t g_w1p[(NFEAT / 2) * NHID];
__device__ __align__(16) uint32_t g_w2t[NHID * W2PN];   // W2 padded, tf32 bits

// ---------------- row_ptr ----------------------------------------------------
__global__ void build_rowptr(const int* __restrict__ rows, int nnz) {
    int i = blockIdx.x * blockDim.x + threadIdx.x;
    if (i > NROWS) return;
    int lo = 0, hi = nnz;
    while (lo < hi) {
        int mid = (lo + hi) >> 1;
        if (rows[mid] < i) lo = mid + 1; else hi = mid;
    }
    g_rowptr[i] = lo;
}

// ---------------- mma helpers -------------------------------------------------
__device__ __forceinline__ uint32_t f2tf32(float a) {
    uint32_t r;
    asm("cvt.rna.tf32.f32 %0, %1;" : "=r"(r) : "f"(a));
    return r;
}
__device__ __forceinline__ void mma_tf32(float* c, const uint32_t* a, const uint32_t* b) {
    asm volatile(
        "mma.sync.aligned.m16n8k8.row.col.f32.tf32.tf32.f32 "
        "{%0,%1,%2,%3}, {%4,%5,%6,%7}, {%8,%9}, {%0,%1,%2,%3};"
        : "+f"(c[0]), "+f"(c[1]), "+f"(c[2]), "+f"(c[3])
        : "r"(a[0]), "r"(a[1]), "r"(a[2]), "r"(a[3]),
          "r"(b[0]), "r"(b[1]));
}
__device__ __forceinline__ void mma_f16(float* c, const uint32_t* a, const uint32_t* b) {
    asm volatile(
        "mma.sync.aligned.m16n8k16.row.col.f32.f16.f16.f32 "
        "{%0,%1,%2,%3}, {%4,%5,%6,%7}, {%8,%9}, {%0,%1,%2,%3};"
        : "+f"(c[0]), "+f"(c[1]), "+f"(c[2]), "+f"(c[3])
        : "r"(a[0]), "r"(a[1]), "r"(a[2]), "r"(a[3]),
          "r"(b[0]), "r"(b[1]));
}

// ---------------- prep: half2-packed W1 / tf32 padded W2 ---------------------
__global__ void prep_w1(const float* __restrict__ w1) {
    int i = blockIdx.x * blockDim.x + threadIdx.x;
    if (i >= (NFEAT / 2) * NHID) return;
    int k2 = i / NHID, n = i % NHID;
    __half2 u = __halves2half2(__float2half_rn(w1[(2 * k2) * NHID + n]),
                               __float2half_rn(w1[(2 * k2 + 1) * NHID + n]));
    g_w1p[i] = *(uint32_t*)&u;
}
__global__ void prep_w2(const float* __restrict__ w2) {
    int i = blockIdx.x * blockDim.x + threadIdx.x;
    if (i >= NHID * W2PN) return;
    int k = i / W2PN, n = i % W2PN;
    g_w2t[i] = (n < NCLASS) ? f2tf32(w2[k * NCLASS + n]) : 0u;
}

// ---------------- SGEMM1: FP16 m16n8k16, double-buffered ---------------------
// Block tile 128x128, K-tile 32 halves (16 half2), 256 threads, 8 warps 2x4.
#define BM 128
#define BN 128
#define FBK 32              // k elements per tile
#define SAP 20              // half2 pitch (16 used): tr*20+tc distinct mod 32
#define SBP 136             // half2 pitch: tc*8+tr distinct mod 32

__device__ __forceinline__ void f_ldgA(const float* A, int row0, int k0, int tid,
                                       float4 ra[4]) {
#pragma unroll
    for (int q = 0; q < 4; q++) {
        int idx = q * 256 + tid;
        int r = idx >> 3, c4 = (idx & 7) * 4;
        float4 v = {0.f, 0.f, 0.f, 0.f};
        if (row0 + r < NROWS)
            v = *(const float4*)(A + (size_t)(row0 + r) * NFEAT + k0 + c4);
        ra[q] = v;
    }
}
__device__ __forceinline__ void f_ldgB(const uint32_t* Bp, int col0, int k0, int tid,
                                       uint4 rb[2]) {
    int k20 = k0 / 2;
#pragma unroll
    for (int q = 0; q < 2; q++) {
        int idx = q * 256 + tid;
        int r = idx >> 5, c4 = (idx & 31) * 4;
        rb[q] = *(const uint4*)(Bp + (size_t)(k20 + r) * NHID + col0 + c4);
    }
}
__device__ __forceinline__ void f_sts(uint32_t (*sA)[SAP], uint32_t (*sB)[SBP],
                                      int tid, const float4 ra[4], const uint4 rb[2]) {
#pragma unroll
    for (int q = 0; q < 4; q++) {
        int idx = q * 256 + tid;
        int r = idx >> 3, c2 = (idx & 7) * 2;
        __half2 h0 = __halves2half2(__float2half_rn(ra[q].x), __float2half_rn(ra[q].y));
        __half2 h1 = __halves2half2(__float2half_rn(ra[q].z), __float2half_rn(ra[q].w));
        sA[r][c2]     = *(uint32_t*)&h0;
        sA[r][c2 + 1] = *(uint32_t*)&h1;
    }
#pragma unroll
    for (int q = 0; q < 2; q++) {
        int idx = q * 256 + tid;
        int r = idx >> 5, c4 = (idx & 31) * 4;
        *(uint4*)&sB[r][c4] = rb[q];
    }
}

__global__ __launch_bounds__(256) void sgemm_f16(const float* __restrict__ A,
                                                 const uint32_t* __restrict__ Bp,
                                                 float* __restrict__ C) {
    __shared__ __align__(16) uint32_t sA[2][BM][SAP];   // half2 units
    __shared__ __align__(16) uint32_t sB[2][FBK / 2][SBP];

    const int tid  = threadIdx.x;
    const int lane = tid & 31;
    const int warp = tid >> 5;
    const int warp_m = warp & 1;
    const int warp_n = warp >> 1;
    const int row0 = blockIdx.x * BM;
    const int col0 = blockIdx.y * BN;
    const int tr = lane >> 2;
    const int tc = lane & 3;

    float acc[4][4][4];
#pragma unroll
    for (int i = 0; i < 4; i++)
#pragma unroll
        for (int j = 0; j < 4; j++)
#pragma unroll
            for (int q = 0; q < 4; q++) acc[i][j][q] = 0.f;

    float4 ra[4]; uint4 rb[2];
    f_ldgA(A, row0, 0, tid, ra);
    f_ldgB(Bp, col0, 0, tid, rb);
    f_sts(sA[0], sB[0], tid, ra, rb);
    __syncthreads();

    const int NT = NFEAT / FBK;   // 16
    for (int t = 0; t < NT; t++) {
        const int cur = t & 1;
        if (t + 1 < NT) {
            f_ldgA(A, row0, (t + 1) * FBK, tid, ra);
            f_ldgB(Bp, col0, (t + 1) * FBK, tid, rb);
        }
#pragma unroll
        for (int s = 0; s < 2; s++) {          // two k16 steps per tile
            const int kb = s * 8;              // half2 base
            uint32_t bf[4][2];
#pragma unroll
            for (int wn = 0; wn < 4; wn++) {
                int n = warp_n * 32 + wn * 8 + tr;
                bf[wn][0] = sB[cur][kb + tc][n];
                bf[wn][1] = sB[cur][kb + tc + 4][n];
            }
#pragma unroll
            for (int wm = 0; wm < 4; wm++) {
                int m = warp_m * 64 + wm * 16 + tr;
                uint32_t af[4];
                af[0] = sA[cur][m][kb + tc];
                af[1] = sA[cur][m + 8][kb + tc];
                af[2] = sA[cur][m][kb + tc + 4];
                af[3] = sA[cur][m + 8][kb + tc + 4];
#pragma unroll
                for (int wn = 0; wn < 4; wn++)
                    mma_f16(acc[wm][wn], af, bf[wn]);
            }
        }
        if (t + 1 < NT)
            f_sts(sA[cur ^ 1], sB[cur ^ 1], tid, ra, rb);
        __syncthreads();
    }

#pragma unroll
    for (int wm = 0; wm < 4; wm++) {
        int r = row0 + warp_m * 64 + wm * 16 + tr;
#pragma unroll
        for (int wn = 0; wn < 4; wn++) {
            int c = col0 + warp_n * 32 + wn * 8 + tc * 2;
            if (r < NROWS) {
                float2 v = {acc[wm][wn][0], acc[wm][wn][1]};
                *(float2*)(C + (size_t)r * NHID + c) = v;
            }
            if (r + 8 < NROWS) {
                float2 v = {acc[wm][wn][2], acc[wm][wn][3]};
                *(float2*)(C + (size_t)(r + 8) * NHID + c) = v;
            }
        }
    }
}

// ---------------- SpMM layer 1 (CSR, warp/row, feature-chunked) --------------
__global__ __launch_bounds__(256) void spmm_chunk(const int* __restrict__ cols,
                                                  const float* __restrict__ vals,
                                                  const float4* __restrict__ dense,
                                                  const float* __restrict__ bias,
                                                  float4* __restrict__ out,
                                                  int chunk) {
    int row  = blockIdx.x * (blockDim.x >> 5) + (threadIdx.x >> 5);
    if (row >= NROWS) return;
    int lane = threadIdx.x & 31;
    const int coff = chunk * 32 + lane;

    int s = g_rowptr[row];
    int e = g_rowptr[row + 1];

    float4 acc = {0.f, 0.f, 0.f, 0.f};
    for (int j = s; j < e; j++) {
        int   c = __ldg(cols + j);
        float v = __ldg(vals + j);
        float4 d = __ldg(dense + (size_t)c * (NHID / 4) + coff);
        acc.x += v * d.x; acc.y += v * d.y; acc.z += v * d.z; acc.w += v * d.w;
    }

    int c0 = coff * 4;
    acc.x = fmaxf(acc.x + __ldg(bias + c0),     0.f);
    acc.y = fmaxf(acc.y + __ldg(bias + c0 + 1), 0.f);
    acc.z = fmaxf(acc.z + __ldg(bias + c0 + 2), 0.f);
    acc.w = fmaxf(acc.w + __ldg(bias + c0 + 3), 0.f);

    out[(size_t)row * (NHID / 4) + coff] = acc;
}

// ---------------- t = h @ W2pad  via TF32 MMA (128x64 tile) ------------------
#define TBM 128
#define TBK 32
#define TSAP 36
#define TSBP 72

__global__ __launch_bounds__(256) void gemm_t_tc(const float* __restrict__ H,
                                                 const uint32_t* __restrict__ Bt,
                                                 float* __restrict__ T) {
    __shared__ __align__(16) uint32_t sA[TBM][TSAP];
    __shared__ __align__(16) uint32_t sB[TBK][TSBP];

    const int tid  = threadIdx.x;
    const int lane = tid & 31;
    const int warp = tid >> 5;
    const int warp_m = warp & 1;
    const int warp_n = warp >> 1;
    const int row0 = blockIdx.x * TBM;
    const int tr = lane >> 2;
    const int tc = lane & 3;

    float acc[4][2][4];
#pragma unroll
    for (int i = 0; i < 4; i++)
#pragma unroll
        for (int j = 0; j < 2; j++)
#pragma unroll
            for (int q = 0; q < 4; q++) acc[i][j][q] = 0.f;

    for (int k0 = 0; k0 < NHID; k0 += TBK) {
#pragma unroll
        for (int q = 0; q < 4; q++) {
            int idx = q * 256 + tid;
            int r = idx >> 3, c4 = (idx & 7) * 4;
            float4 v = {0.f, 0.f, 0.f, 0.f};
            if (row0 + r < NROWS)
                v = *(const float4*)(H + (size_t)(row0 + r) * NHID + k0 + c4);
            uint4 u = {f2tf32(v.x), f2tf32(v.y), f2tf32(v.z), f2tf32(v.w)};
            *(uint4*)&sA[r][c4] = u;
        }
#pragma unroll
        for (int q = 0; q < 2; q++) {
            int idx = q * 256 + tid;
            int r = idx >> 4, c4 = (idx & 15) * 4;
            *(uint4*)&sB[r][c4] = *(const uint4*)(Bt + (size_t)(k0 + r) * W2PN + c4);
        }
        __syncthreads();

#pragma unroll
        for (int kk = 0; kk < TBK; kk += 8) {
            uint32_t bf[2][2];
#pragma unroll
            for (int wn = 0; wn < 2; wn++) {
                int n = warp_n * 16 + wn * 8 + tr;
                bf[wn][0] = sB[kk + tc][n];
                bf[wn][1] = sB[kk + tc + 4][n];
            }
#pragma unroll
            for (int wm = 0; wm < 4; wm++) {
                int m = warp_m * 64 + wm * 16 + tr;
                uint32_t af[4];
                af[0] = sA[m][kk + tc];
                af[1] = sA[m + 8][kk + tc];
                af[2] = sA[m][kk + tc + 4];
                af[3] = sA[m + 8][kk + tc + 4];
#pragma unroll
                for (int wn = 0; wn < 2; wn++)
                    mma_tf32(acc[wm][wn], af, bf[wn]);
            }
        }
        __syncthreads();
    }

#pragma unroll
    for (int wm = 0; wm < 4; wm++) {
        int r = row0 + warp_m * 64 + wm * 16 + tr;
#pragma unroll
        for (int wn = 0; wn < 2; wn++) {
            int c = warp_n * 16 + wn * 8 + tc * 2;
            if (c < TPAD) {
                if (r < NROWS) {
                    float2 v = {acc[wm][wn][0], acc[wm][wn][1]};
                    *(float2*)(T + (size_t)r * TPAD + c) = v;
                }
                if (r + 8 < NROWS) {
                    float2 v = {acc[wm][wn][2], acc[wm][wn][3]};
                    *(float2*)(T + (size_t)(r + 8) * TPAD + c) = v;
                }
            }
        }
    }
}

// ---------------- SpMM layer 2 + b2 + log_softmax, fused ---------------------
__global__ __launch_bounds__(256) void spmm2_lsm(const int* __restrict__ cols,
                                                 const float* __restrict__ vals,
                                                 const float4* __restrict__ t,
                                                 const float* __restrict__ b2,
                                                 float* __restrict__ out) {
    int row  = blockIdx.x * (blockDim.x >> 5) + (threadIdx.x >> 5);
    if (row >= NROWS) return;
    int lane = threadIdx.x & 31;
    const bool active = lane < (TPAD / 4);

    int s = g_rowptr[row];
    int e = g_rowptr[row + 1];

    float4 acc = {0.f, 0.f, 0.f, 0.f};
    for (int j = s; j < e; j++) {
        int   c = __ldg(cols + j);
        float v = __ldg(vals + j);
        if (active) {
            float4 d = __ldg(t + (size_t)c * (TPAD / 4) + lane);
            acc.x += v * d.x; acc.y += v * d.y; acc.z += v * d.z; acc.w += v * d.w;
        }
    }

    float z[4];
    const int c0 = lane * 4;
#pragma unroll
    for (int i = 0; i < 4; i++) {
        int c = c0 + i;
        z[i] = (c < NCLASS) ? ((&acc.x)[i] + __ldg(b2 + c)) : -INFINITY;
    }
    float m = fmaxf(fmaxf(z[0], z[1]), fmaxf(z[2], z[3]));
#pragma unroll
    for (int off = 16; off; off >>= 1)
        m = fmaxf(m, __shfl_xor_sync(0xFFFFFFFFu, m, off));

    float ss = 0.f;
#pragma unroll
    for (int i = 0; i < 4; i++)
        if (c0 + i < NCLASS) ss += expf(z[i] - m);
#pragma unroll
    for (int off = 16; off; off >>= 1)
        ss += __shfl_xor_sync(0xFFFFFFFFu, ss, off);

    float lse = m + logf(ss);
#pragma unroll
    for (int i = 0; i < 4; i++) {
        int c = c0 + i;
        if (c < NCLASS) out[(size_t)row * NCLASS + c] = z[i] - lse;
    }
}

// -----------------------------------------------------------------------------
extern "C" void kernel_launch(void* const* d_in, const int* in_sizes, int n_in,
                              void* d_out, int out_size) {
    const float* x        = (const float*)d_in[0];
    const int*   adj_rows = (const int*)  d_in[1];
    const int*   adj_cols = (const int*)  d_in[2];
    const float* adj_vals = (const float*)d_in[3];
    const float* w1       = (const float*)d_in[4];
    const float* b1       = (const float*)d_in[5];
    const float* w2       = (const float*)d_in[6];
    const float* b2       = (const float*)d_in[7];
    float* out = (float*)d_out;
    const int nnz = in_sizes[1];

    float4* buf1; cudaGetSymbolAddress((void**)&buf1, g_buf1_v);
    float4* buf2; cudaGetSymbolAddress((void**)&buf2, g_buf2_v);
    uint32_t* w1p; cudaGetSymbolAddress((void**)&w1p, g_w1p);
    uint32_t* w2t; cudaGetSymbolAddress((void**)&w2t, g_w2t);

    // 1) CSR row pointers + weight images
    build_rowptr<<<(NROWS + 1 + 255) / 256, 256>>>(adj_rows, nnz);
    prep_w1<<<((NFEAT / 2) * NHID + 255) / 256, 256>>>(w1);
    prep_w2<<<(NHID * W2PN + 255) / 256, 256>>>(w2);

    // 2) XW1 -> buf1 (FP16 m16n8k16, double-buffered)
    dim3 g1((NROWS + BM - 1) / BM, NHID / BN);
    sgemm_f16<<<g1, 256>>>(x, w1p, (float*)buf1);

    // 3) h = relu(A @ buf1 + b1) -> buf2  (two L2-resident feature chunks)
    int spmm_blocks = (NROWS * 32 + 255) / 256;
    spmm_chunk<<<spmm_blocks, 256>>>(adj_cols, adj_vals, buf1, b1, buf2, 0);
    spmm_chunk<<<spmm_blocks, 256>>>(adj_cols, adj_vals, buf1, b1, buf2, 1);

    // 4) t = h @ W2pad -> buf1 (44-pitch, TF32 MMA)
    gemm_t_tc<<<(NROWS + TBM - 1) / TBM, 256>>>((const float*)buf2, w2t, (float*)buf1);

    // 5) out = log_softmax(A @ t + b2)   (t: 17.6MB, L2-resident)
    spmm2_lsm<<<spmm_blocks, 256>>>(adj_cols, adj_vals, buf1, b2, out);
}

// round 12
// speedup vs baseline: 5.9247x; 1.3883x over previous
#include <cuda_runtime.h>
#include <cuda_fp16.h>
#include <cstdint>
#include <math.h>

#define NROWS   100000
#define NFEAT   512
#define NHID    256
#define NCLASS  41
#define TPH     48          // t row pitch in halves (41 used)
#define W2PN    64          // W2 padded cols

// ---------------- scratch (device globals) ----------------------------------
__device__ float4 g_buf1_v[(size_t)NROWS * NHID / 4];   // XW1 (half), then t (half)
__device__ float4 g_buf2_v[(size_t)NROWS * NHID / 4];   // h (half)
__device__ int    g_rowptr[NROWS + 1];
// W1 packed as half2 along k: g_w1p[k2 * NHID + n] = (w1[2k2][n], w1[2k2+1][n])
__device__ __align__(16) uint32_t g_w1p[(NFEAT / 2) * NHID];
// W2 packed as half2 along k, padded to 64 cols
__device__ __align__(16) uint32_t g_w2p[(NHID / 2) * W2PN];

// ---------------- row_ptr ----------------------------------------------------
__global__ void build_rowptr(const int* __restrict__ rows, int nnz) {
    int i = blockIdx.x * blockDim.x + threadIdx.x;
    if (i > NROWS) return;
    int lo = 0, hi = nnz;
    while (lo < hi) {
        int mid = (lo + hi) >> 1;
        if (rows[mid] < i) lo = mid + 1; else hi = mid;
    }
    g_rowptr[i] = lo;
}

// ---------------- mma helper ---------------------------------------------------
__device__ __forceinline__ void mma_f16(float* c, const uint32_t* a, const uint32_t* b) {
    asm volatile(
        "mma.sync.aligned.m16n8k16.row.col.f32.f16.f16.f32 "
        "{%0,%1,%2,%3}, {%4,%5,%6,%7}, {%8,%9}, {%0,%1,%2,%3};"
        : "+f"(c[0]), "+f"(c[1]), "+f"(c[2]), "+f"(c[3])
        : "r"(a[0]), "r"(a[1]), "r"(a[2]), "r"(a[3]),
          "r"(b[0]), "r"(b[1]));
}

// ---------------- prep: half2-packed W1 / W2 ---------------------------------
__global__ void prep_w1(const float* __restrict__ w1) {
    int i = blockIdx.x * blockDim.x + threadIdx.x;
    if (i >= (NFEAT / 2) * NHID) return;
    int k2 = i / NHID, n = i % NHID;
    __half2 u = __halves2half2(__float2half_rn(w1[(2 * k2) * NHID + n]),
                               __float2half_rn(w1[(2 * k2 + 1) * NHID + n]));
    g_w1p[i] = *(uint32_t*)&u;
}
__global__ void prep_w2(const float* __restrict__ w2) {
    int i = blockIdx.x * blockDim.x + threadIdx.x;
    if (i >= (NHID / 2) * W2PN) return;
    int k2 = i / W2PN, n = i % W2PN;
    __half2 u = (n < NCLASS)
        ? __halves2half2(__float2half_rn(w2[(2 * k2) * NCLASS + n]),
                         __float2half_rn(w2[(2 * k2 + 1) * NCLASS + n]))
        : __halves2half2(__float2half_rn(0.f), __float2half_rn(0.f));
    g_w2p[i] = *(uint32_t*)&u;
}

// ---------------- SGEMM1: FP16 m16n8k16, double-buffered, half out -----------
#define BM 128
#define BN 128
#define FBK 32
#define SAP 20
#define SBP 136

__device__ __forceinline__ void f_ldgA(const float* A, int row0, int k0, int tid,
                                       float4 ra[4]) {
#pragma unroll
    for (int q = 0; q < 4; q++) {
        int idx = q * 256 + tid;
        int r = idx >> 3, c4 = (idx & 7) * 4;
        float4 v = {0.f, 0.f, 0.f, 0.f};
        if (row0 + r < NROWS)
            v = *(const float4*)(A + (size_t)(row0 + r) * NFEAT + k0 + c4);
        ra[q] = v;
    }
}
__device__ __forceinline__ void f_ldgB(const uint32_t* Bp, int col0, int k0, int tid,
                                       uint4 rb[2]) {
    int k20 = k0 / 2;
#pragma unroll
    for (int q = 0; q < 2; q++) {
        int idx = q * 256 + tid;
        int r = idx >> 5, c4 = (idx & 31) * 4;
        rb[q] = *(const uint4*)(Bp + (size_t)(k20 + r) * NHID + col0 + c4);
    }
}
__device__ __forceinline__ void f_sts(uint32_t (*sA)[SAP], uint32_t (*sB)[SBP],
                                      int tid, const float4 ra[4], const uint4 rb[2]) {
#pragma unroll
    for (int q = 0; q < 4; q++) {
        int idx = q * 256 + tid;
        int r = idx >> 3, c2 = (idx & 7) * 2;
        __half2 h0 = __floats2half2_rn(ra[q].x, ra[q].y);
        __half2 h1 = __floats2half2_rn(ra[q].z, ra[q].w);
        sA[r][c2]     = *(uint32_t*)&h0;
        sA[r][c2 + 1] = *(uint32_t*)&h1;
    }
#pragma unroll
    for (int q = 0; q < 2; q++) {
        int idx = q * 256 + tid;
        int r = idx >> 5, c4 = (idx & 31) * 4;
        *(uint4*)&sB[r][c4] = rb[q];
    }
}

__global__ __launch_bounds__(256) void sgemm_f16(const float* __restrict__ A,
                                                 const uint32_t* __restrict__ Bp,
                                                 __half* __restrict__ C) {
    __shared__ __align__(16) uint32_t sA[2][BM][SAP];
    __shared__ __align__(16) uint32_t sB[2][FBK / 2][SBP];

    const int tid  = threadIdx.x;
    const int lane = tid & 31;
    const int warp = tid >> 5;
    const int warp_m = warp & 1;
    const int warp_n = warp >> 1;
    const int row0 = blockIdx.y * BM;     // grid swapped: y=row, x=col
    const int col0 = blockIdx.x * BN;
    const int tr = lane >> 2;
    const int tc = lane & 3;

    float acc[4][4][4];
#pragma unroll
    for (int i = 0; i < 4; i++)
#pragma unroll
        for (int j = 0; j < 4; j++)
#pragma unroll
            for (int q = 0; q < 4; q++) acc[i][j][q] = 0.f;

    float4 ra[4]; uint4 rb[2];
    f_ldgA(A, row0, 0, tid, ra);
    f_ldgB(Bp, col0, 0, tid, rb);
    f_sts(sA[0], sB[0], tid, ra, rb);
    __syncthreads();

    const int NT = NFEAT / FBK;
    for (int t = 0; t < NT; t++) {
        const int cur = t & 1;
        if (t + 1 < NT) {
            f_ldgA(A, row0, (t + 1) * FBK, tid, ra);
            f_ldgB(Bp, col0, (t + 1) * FBK, tid, rb);
        }
#pragma unroll
        for (int s = 0; s < 2; s++) {
            const int kb = s * 8;
            uint32_t bf[4][2];
#pragma unroll
            for (int wn = 0; wn < 4; wn++) {
                int n = warp_n * 32 + wn * 8 + tr;
                bf[wn][0] = sB[cur][kb + tc][n];
                bf[wn][1] = sB[cur][kb + tc + 4][n];
            }
#pragma unroll
            for (int wm = 0; wm < 4; wm++) {
                int m = warp_m * 64 + wm * 16 + tr;
                uint32_t af[4];
                af[0] = sA[cur][m][kb + tc];
                af[1] = sA[cur][m + 8][kb + tc];
                af[2] = sA[cur][m][kb + tc + 4];
                af[3] = sA[cur][m + 8][kb + tc + 4];
#pragma unroll
                for (int wn = 0; wn < 4; wn++)
                    mma_f16(acc[wm][wn], af, bf[wn]);
            }
        }
        if (t + 1 < NT)
            f_sts(sA[cur ^ 1], sB[cur ^ 1], tid, ra, rb);
        __syncthreads();
    }

#pragma unroll
    for (int wm = 0; wm < 4; wm++) {
        int r = row0 + warp_m * 64 + wm * 16 + tr;
#pragma unroll
        for (int wn = 0; wn < 4; wn++) {
            int c = col0 + warp_n * 32 + wn * 8 + tc * 2;
            if (r < NROWS) {
                __half2 hv = __floats2half2_rn(acc[wm][wn][0], acc[wm][wn][1]);
                *(uint32_t*)(C + (size_t)r * NHID + c) = *(uint32_t*)&hv;
            }
            if (r + 8 < NROWS) {
                __half2 hv = __floats2half2_rn(acc[wm][wn][2], acc[wm][wn][3]);
                *(uint32_t*)(C + (size_t)(r + 8) * NHID + c) = *(uint32_t*)&hv;
            }
        }
    }
}

// ---------------- SpMM layer 1: fp16 rows, single pass -----------------------
// warp per row; lane covers 8 halves (one uint4). fp32 accumulate; half out.
__global__ __launch_bounds__(256) void spmm1_h(const int* __restrict__ cols,
                                               const float* __restrict__ vals,
                                               const uint4* __restrict__ denseH,
                                               const float* __restrict__ bias,
                                               uint4* __restrict__ outH) {
    int row  = blockIdx.x * 8 + (threadIdx.x >> 5);
    if (row >= NROWS) return;
    int lane = threadIdx.x & 31;

    int s = g_rowptr[row];
    int e = g_rowptr[row + 1];

    float acc[8];
#pragma unroll
    for (int i = 0; i < 8; i++) acc[i] = 0.f;

    for (int j = s; j < e; j++) {
        int   c = __ldg(cols + j);
        float v = __ldg(vals + j);
        uint4 d = __ldg(denseH + (size_t)c * (NHID / 8) + lane);
        const uint32_t* dw = (const uint32_t*)&d;
#pragma unroll
        for (int i = 0; i < 4; i++) {
            float2 f = __half22float2(*(const __half2*)&dw[i]);
            acc[2 * i]     += v * f.x;
            acc[2 * i + 1] += v * f.y;
        }
    }

    const int c0 = lane * 8;
    float4 b0 = __ldg((const float4*)(bias + c0));
    float4 b1 = __ldg((const float4*)(bias + c0 + 4));
    acc[0] = fmaxf(acc[0] + b0.x, 0.f); acc[1] = fmaxf(acc[1] + b0.y, 0.f);
    acc[2] = fmaxf(acc[2] + b0.z, 0.f); acc[3] = fmaxf(acc[3] + b0.w, 0.f);
    acc[4] = fmaxf(acc[4] + b1.x, 0.f); acc[5] = fmaxf(acc[5] + b1.y, 0.f);
    acc[6] = fmaxf(acc[6] + b1.z, 0.f); acc[7] = fmaxf(acc[7] + b1.w, 0.f);

    uint4 o;
    uint32_t* ow = (uint32_t*)&o;
#pragma unroll
    for (int i = 0; i < 4; i++) {
        __half2 hv = __floats2half2_rn(acc[2 * i], acc[2 * i + 1]);
        ow[i] = *(uint32_t*)&hv;
    }
    outH[(size_t)row * (NHID / 8) + lane] = o;
}

// ---------------- t = h @ W2  fp16 m16n8k16 (128x64 tile) --------------------
#define TBM 128
#define TBK 64      // halves per k-tile
#define TSAP 36     // half2 pitch (32 used)
#define TSBP 72     // uint32 pitch (64 used)

__global__ __launch_bounds__(256) void gemm_t_h(const __half* __restrict__ H,
                                                const uint32_t* __restrict__ Bp,
                                                __half* __restrict__ T) {
    __shared__ __align__(16) uint32_t sA[TBM][TSAP];
    __shared__ __align__(16) uint32_t sB[TBK / 2][TSBP];

    const int tid  = threadIdx.x;
    const int lane = tid & 31;
    const int warp = tid >> 5;
    const int warp_m = warp & 1;     // 64 rows each
    const int warp_n = warp >> 1;    // 16 cols each
    const int row0 = blockIdx.x * TBM;
    const int tr = lane >> 2;
    const int tc = lane & 3;

    float acc[4][2][4];
#pragma unroll
    for (int i = 0; i < 4; i++)
#pragma unroll
        for (int j = 0; j < 2; j++)
#pragma unroll
            for (int q = 0; q < 4; q++) acc[i][j][q] = 0.f;

    for (int k0 = 0; k0 < NHID; k0 += TBK) {
        // A: 128 x 64 halves = 1024 uint4, 4/thread (raw half copies)
#pragma unroll
        for (int q = 0; q < 4; q++) {
            int idx = q * 256 + tid;
            int r = idx >> 3, c8 = (idx & 7) * 8;      // halves
            uint4 v = {0u, 0u, 0u, 0u};
            if (row0 + r < NROWS)
                v = *(const uint4*)(H + (size_t)(row0 + r) * NHID + k0 + c8);
            *(uint4*)&sA[r][c8 / 2] = v;
        }
        // B: 32 packed rows x 64 = 512 uint4, 2/thread
        {
            int k20 = k0 / 2;
#pragma unroll
            for (int q = 0; q < 2; q++) {
                int idx = q * 256 + tid;
                int r = idx >> 4, c4 = (idx & 15) * 4;
                *(uint4*)&sB[r][c4] = *(const uint4*)(Bp + (size_t)(k20 + r) * W2PN + c4);
            }
        }
        __syncthreads();

#pragma unroll
        for (int s = 0; s < 4; s++) {       // 4 k16 steps per tile
            const int kb = s * 8;           // half2 base
            uint32_t bf[2][2];
#pragma unroll
            for (int wn = 0; wn < 2; wn++) {
                int n = warp_n * 16 + wn * 8 + tr;
                bf[wn][0] = sB[kb + tc][n];
                bf[wn][1] = sB[kb + tc + 4][n];
            }
#pragma unroll
            for (int wm = 0; wm < 4; wm++) {
                int m = warp_m * 64 + wm * 16 + tr;
                uint32_t af[4];
                af[0] = sA[m][kb + tc];
                af[1] = sA[m + 8][kb + tc];
                af[2] = sA[m][kb + tc + 4];
                af[3] = sA[m + 8][kb + tc + 4];
#pragma unroll
                for (int wn = 0; wn < 2; wn++)
                    mma_f16(acc[wm][wn], af, bf[wn]);
            }
        }
        __syncthreads();
    }

    // epilogue -> half t rows, pitch TPH (cols >= TPH dropped; 41..47 zero pad)
#pragma unroll
    for (int wm = 0; wm < 4; wm++) {
        int r = row0 + warp_m * 64 + wm * 16 + tr;
#pragma unroll
        for (int wn = 0; wn < 2; wn++) {
            int c = warp_n * 16 + wn * 8 + tc * 2;
            if (c < TPH) {
                if (r < NROWS) {
                    __half2 hv = __floats2half2_rn(acc[wm][wn][0], acc[wm][wn][1]);
                    *(uint32_t*)(T + (size_t)r * TPH + c) = *(uint32_t*)&hv;
                }
                if (r + 8 < NROWS) {
                    __half2 hv = __floats2half2_rn(acc[wm][wn][2], acc[wm][wn][3]);
                    *(uint32_t*)(T + (size_t)(r + 8) * TPH + c) = *(uint32_t*)&hv;
                }
            }
        }
    }
}

// ---------------- SpMM layer 2 + b2 + log_softmax (fp16 t) -------------------
// t rows: 48 halves (96B). lanes 0..11 gather uint2 (4 halves) each.
__global__ __launch_bounds__(256) void spmm2_lsm(const int* __restrict__ cols,
                                                 const float* __restrict__ vals,
                                                 const uint2* __restrict__ tH,
                                                 const float* __restrict__ b2,
                                                 float* __restrict__ out) {
    int row  = blockIdx.x * 8 + (threadIdx.x >> 5);
    if (row >= NROWS) return;
    int lane = threadIdx.x & 31;
    const bool active = lane < (TPH / 4);    // 12 lanes

    int s = g_rowptr[row];
    int e = g_rowptr[row + 1];

    float acc[4] = {0.f, 0.f, 0.f, 0.f};
    for (int j = s; j < e; j++) {
        int   c = __ldg(cols + j);
        float v = __ldg(vals + j);
        if (active) {
            uint2 d = __ldg(tH + (size_t)c * (TPH / 4) + lane);
            float2 f0 = __half22float2(*(const __half2*)&d.x);
            float2 f1 = __half22float2(*(const __half2*)&d.y);
            acc[0] += v * f0.x; acc[1] += v * f0.y;
            acc[2] += v * f1.x; acc[3] += v * f1.y;
        }
    }

    float z[4];
    const int c0 = lane * 4;
#pragma unroll
    for (int i = 0; i < 4; i++) {
        int c = c0 + i;
        z[i] = (active && c < NCLASS) ? (acc[i] + __ldg(b2 + c)) : -INFINITY;
    }
    float m = fmaxf(fmaxf(z[0], z[1]), fmaxf(z[2], z[3]));
#pragma unroll
    for (int off = 16; off; off >>= 1)
        m = fmaxf(m, __shfl_xor_sync(0xFFFFFFFFu, m, off));

    float ss = 0.f;
#pragma unroll
    for (int i = 0; i < 4; i++)
        if (c0 + i < NCLASS) ss += expf(z[i] - m);
#pragma unroll
    for (int off = 16; off; off >>= 1)
        ss += __shfl_xor_sync(0xFFFFFFFFu, ss, off);

    float lse = m + logf(ss);
#pragma unroll
    for (int i = 0; i < 4; i++) {
        int c = c0 + i;
        if (c < NCLASS) out[(size_t)row * NCLASS + c] = z[i] - lse;
    }
}

// -----------------------------------------------------------------------------
extern "C" void kernel_launch(void* const* d_in, const int* in_sizes, int n_in,
                              void* d_out, int out_size) {
    const float* x        = (const float*)d_in[0];
    const int*   adj_rows = (const int*)  d_in[1];
    const int*   adj_cols = (const int*)  d_in[2];
    const float* adj_vals = (const float*)d_in[3];
    const float* w1       = (const float*)d_in[4];
    const float* b1       = (const float*)d_in[5];
    const float* w2       = (const float*)d_in[6];
    const float* b2       = (const float*)d_in[7];
    float* out = (float*)d_out;
    const int nnz = in_sizes[1];

    void* buf1; cudaGetSymbolAddress(&buf1, g_buf1_v);
    void* buf2; cudaGetSymbolAddress(&buf2, g_buf2_v);
    uint32_t* w1p; cudaGetSymbolAddress((void**)&w1p, g_w1p);
    uint32_t* w2p; cudaGetSymbolAddress((void**)&w2p, g_w2p);

    // 1) CSR row pointers + packed weights
    build_rowptr<<<(NROWS + 1 + 255) / 256, 256>>>(adj_rows, nnz);
    prep_w1<<<((NFEAT / 2) * NHID + 255) / 256, 256>>>(w1);
    prep_w2<<<((NHID / 2) * W2PN + 255) / 256, 256>>>(w2);

    // 2) XW1 -> buf1 (half). grid: x=col tiles (2), y=row tiles -> A L2 reuse
    dim3 g1(NHID / BN, (NROWS + BM - 1) / BM);
    sgemm_f16<<<g1, 256>>>(x, w1p, (__half*)buf1);

    // 3) h = relu(A @ XW1 + b1) -> buf2 (half), single pass
    int spmm_blocks = (NROWS + 7) / 8;
    spmm1_h<<<spmm_blocks, 256>>>(adj_cols, adj_vals, (const uint4*)buf1, b1,
                                  (uint4*)buf2);

    // 4) t = h @ W2 -> buf1 (half, 48-pitch)
    gemm_t_h<<<(NROWS + TBM - 1) / TBM, 256>>>((const __half*)buf2, w2p,
                                               (__half*)buf1);

    // 5) out = log_softmax(A @ t + b2)   (t: 9.6MB, L2-resident)
    spmm2_lsm<<<spmm_blocks, 256>>>(adj_cols, adj_vals, (const uint2*)buf1, b2, out);
}